// round 1
// baseline (speedup 1.0000x reference)
#include <cuda_runtime.h>

// Problem constants: x (8, 512, 32, 32) -> (b=8, c=512, t=1024)
#define BB 8
#define CC 512
#define TT 1024
#define NHEADS 8
#define CHD 64
#define NGRP 32
#define CPG 16   // channels per group

// Scratch (alloc-free rule: __device__ globals)
__device__ float g_h[BB * CC * TT];        // groupnorm output   (16.8 MB)
__device__ float g_qkv[BB * 3 * CC * TT];  // qkv projections    (50.3 MB)
__device__ float g_a[BB * CC * TT];        // attention output   (16.8 MB)

// ---------------------------------------------------------------------------
// GroupNorm: one block per (batch, group). Group data is 16 ch x 1024 t =
// 16384 contiguous floats (channels are contiguous within a group).
// ---------------------------------------------------------------------------
__global__ __launch_bounds__(256) void gn_kernel(const float* __restrict__ x,
                                                 const float* __restrict__ gamma,
                                                 const float* __restrict__ beta) {
    int bg = blockIdx.x;                       // b*32 + g
    const float* src = x + (size_t)bg * (CPG * TT);
    float* dst = g_h + (size_t)bg * (CPG * TT);
    int tid = threadIdx.x;

    float s = 0.f, ss = 0.f;
    for (int i = tid * 4; i < CPG * TT; i += 256 * 4) {
        float4 v = *(const float4*)(src + i);
        s  += v.x + v.y + v.z + v.w;
        ss += v.x * v.x + v.y * v.y + v.z * v.z + v.w * v.w;
    }
    #pragma unroll
    for (int off = 16; off; off >>= 1) {
        s  += __shfl_xor_sync(0xffffffffu, s, off);
        ss += __shfl_xor_sync(0xffffffffu, ss, off);
    }
    __shared__ float ws[8], wss[8];
    __shared__ float sh_mean, sh_r;
    int warp = tid >> 5, lane = tid & 31;
    if (lane == 0) { ws[warp] = s; wss[warp] = ss; }
    __syncthreads();
    if (tid == 0) {
        float S = 0.f, SS = 0.f;
        #pragma unroll
        for (int i = 0; i < 8; i++) { S += ws[i]; SS += wss[i]; }
        const float inv_n = 1.f / (CPG * TT);
        float mean = S * inv_n;
        float var  = SS * inv_n - mean * mean;
        sh_mean = mean;
        sh_r = rsqrtf(var + 1e-5f);
    }
    __syncthreads();
    float mean = sh_mean, r = sh_r;
    int g = bg & (NGRP - 1);
    for (int i = tid * 4; i < CPG * TT; i += 256 * 4) {
        int ch = g * CPG + (i >> 10);          // all 4 lanes of float4 share ch
        float gm = gamma[ch] * r;
        float bt = beta[ch] - mean * gm;
        float4 v = *(const float4*)(src + i);
        float4 o;
        o.x = v.x * gm + bt; o.y = v.y * gm + bt;
        o.z = v.z * gm + bt; o.w = v.w * gm + bt;
        *(float4*)(dst + i) = o;
    }
}

// ---------------------------------------------------------------------------
// Tiled fp32 GEMM: Out[b,o,t] = sum_c W[o,c]*X[b,c,t] + bias[o] (+ resid)
// 64x64 output tile, K-tile 16, 256 threads, 4x4 per-thread micro-tile.
// grid: (t/64, Odim/64, batch)
// ---------------------------------------------------------------------------
template <bool RES>
__global__ __launch_bounds__(256) void gemm_kernel(const float* __restrict__ W,
                                                   const float* __restrict__ X,
                                                   const float* __restrict__ bias,
                                                   const float* __restrict__ resid,
                                                   float* __restrict__ Out,
                                                   int Odim) {
    __shared__ float Ws[16][68];   // [k][m], padded: conflict-free transposed stores
    __shared__ float Xs[16][64];   // [k][n]

    int b  = blockIdx.z;
    const float* Xb = X + (size_t)b * CC * TT;
    int t0 = blockIdx.x << 6, o0 = blockIdx.y << 6;
    int tid = threadIdx.x;
    int tx = tid & 15, ty = tid >> 4;
    int wm = tid >> 2, wk = (tid & 3) << 2;    // W tile: 64 rows x 16 k
    int xk = tid >> 4, xn = (tid & 15) << 2;   // X tile: 16 k x 64 n

    float acc[4][4] = {};

    for (int c0 = 0; c0 < CC; c0 += 16) {
        float4 wv = *(const float4*)(W + (size_t)(o0 + wm) * CC + c0 + wk);
        Ws[wk + 0][wm] = wv.x; Ws[wk + 1][wm] = wv.y;
        Ws[wk + 2][wm] = wv.z; Ws[wk + 3][wm] = wv.w;
        *(float4*)&Xs[xk][xn] =
            *(const float4*)(Xb + (size_t)(c0 + xk) * TT + t0 + xn);
        __syncthreads();
        #pragma unroll
        for (int k = 0; k < 16; k++) {
            float4 a4 = *(const float4*)&Ws[k][ty << 2];
            float4 b4 = *(const float4*)&Xs[k][tx << 2];
            float av[4] = {a4.x, a4.y, a4.z, a4.w};
            float bv[4] = {b4.x, b4.y, b4.z, b4.w};
            #pragma unroll
            for (int r = 0; r < 4; r++)
                #pragma unroll
                for (int u = 0; u < 4; u++)
                    acc[r][u] = fmaf(av[r], bv[u], acc[r][u]);
        }
        __syncthreads();
    }

    float* Ob = Out + (size_t)b * Odim * TT;
    const float* Rb = resid + (size_t)b * Odim * TT;   // dead if !RES
    #pragma unroll
    for (int r = 0; r < 4; r++) {
        int o = o0 + (ty << 2) + r;
        float bs = bias[o];
        size_t off = (size_t)o * TT + t0 + (tx << 2);
        float4 ov;
        ov.x = acc[r][0] + bs; ov.y = acc[r][1] + bs;
        ov.z = acc[r][2] + bs; ov.w = acc[r][3] + bs;
        if (RES) {
            float4 rv = *(const float4*)(Rb + off);
            ov.x += rv.x; ov.y += rv.y; ov.z += rv.z; ov.w += rv.w;
        }
        *(float4*)(Ob + off) = ov;
    }
}

// ---------------------------------------------------------------------------
// Flash attention, fp32. One block = (head, 64-query tile). 256 threads
// arranged 16x16; each thread owns 4 query rows x 4 (keys | channels).
// Layout in g_qkv per head: rows [h*192, h*192+64)=Q, +64..128=K, +128..192=V,
// each [64ch x 1024t] channel-major.
// ---------------------------------------------------------------------------
#define ATTN_SMEM ((4096 * 3 + 64 * 65) * 4)   // Qs+Ks+Ps + padded Vs = 65792 B

__global__ __launch_bounds__(256) void attn_kernel() {
    extern __shared__ float sm[];
    float* Qs = sm;               // [64c][64i]
    float* Ks = Qs + 4096;        // [64c][64j]
    float* Vs = Ks + 4096;        // [64c][65]  (pad -> 2-way worst conflicts)
    float* Ps = Vs + 64 * 65;     // [64i][64j]

    int it = blockIdx.x;          // query tile 0..15
    int hd = blockIdx.y;          // 0..63
    int bbi = hd >> 3, hh = hd & 7;
    const float* qb = g_qkv + (size_t)bbi * (3 * CC * TT) + (size_t)(hh * 3 * CHD) * TT;
    const float* kb = qb + CHD * TT;
    const float* vb = kb + CHD * TT;
    int t0 = it << 6;
    int tid = threadIdx.x, tx = tid & 15, ty = tid >> 4;

    for (int e = tid * 4; e < 4096; e += 1024) {
        int c = e >> 6, i = e & 63;
        *(float4*)&Qs[c * 64 + i] = *(const float4*)(qb + (size_t)c * TT + t0 + i);
    }

    float m[4] = {-1e30f, -1e30f, -1e30f, -1e30f};
    float l[4] = {};
    float O[4][4] = {};

    for (int s0 = 0; s0 < TT; s0 += 64) {
        __syncthreads();   // prior PV / prior Ps consumers done before overwrite
        for (int e = tid * 4; e < 4096; e += 1024) {
            int c = e >> 6, j = e & 63;
            *(float4*)&Ks[c * 64 + j] = *(const float4*)(kb + (size_t)c * TT + s0 + j);
            float4 vv = *(const float4*)(vb + (size_t)c * TT + s0 + j);
            float* vp = &Vs[c * 65 + j];
            vp[0] = vv.x; vp[1] = vv.y; vp[2] = vv.z; vp[3] = vv.w;
        }
        __syncthreads();

        // S = Q^T K (inner dim = 64 channels)
        float sc[4][4] = {};
        #pragma unroll 8
        for (int c = 0; c < 64; c++) {
            float4 q4 = *(const float4*)&Qs[c * 64 + (ty << 2)];
            float4 k4 = *(const float4*)&Ks[c * 64 + (tx << 2)];
            float qv[4] = {q4.x, q4.y, q4.z, q4.w};
            float kv[4] = {k4.x, k4.y, k4.z, k4.w};
            #pragma unroll
            for (int r = 0; r < 4; r++)
                #pragma unroll
                for (int u = 0; u < 4; u++)
                    sc[r][u] = fmaf(qv[r], kv[u], sc[r][u]);
        }

        // online softmax per query row (16 tx lanes per row group, in-warp)
        #pragma unroll
        for (int r = 0; r < 4; r++) {
            float mx = -1e30f;
            #pragma unroll
            for (int u = 0; u < 4; u++) {
                sc[r][u] *= 0.125f;            // scale^2 = 1/sqrt(64)
                mx = fmaxf(mx, sc[r][u]);
            }
            #pragma unroll
            for (int off = 8; off; off >>= 1)
                mx = fmaxf(mx, __shfl_xor_sync(0xffffffffu, mx, off));
            float mn = fmaxf(m[r], mx);
            float corr = __expf(m[r] - mn);
            m[r] = mn;
            float rs = 0.f;
            #pragma unroll
            for (int u = 0; u < 4; u++) {
                float p = __expf(sc[r][u] - mn);
                sc[r][u] = p;
                rs += p;
            }
            #pragma unroll
            for (int off = 8; off; off >>= 1)
                rs += __shfl_xor_sync(0xffffffffu, rs, off);
            l[r] = l[r] * corr + rs;
            #pragma unroll
            for (int u = 0; u < 4; u++) O[r][u] *= corr;
            *(float4*)&Ps[(ty * 4 + r) * 64 + (tx << 2)] =
                make_float4(sc[r][0], sc[r][1], sc[r][2], sc[r][3]);
        }
        __syncthreads();

        // O[i][c] += sum_j P[i][j] * V[c][j]
        #pragma unroll 4
        for (int j = 0; j < 64; j++) {
            float pr[4], vv[4];
            #pragma unroll
            for (int r = 0; r < 4; r++) pr[r] = Ps[(ty * 4 + r) * 64 + j];  // broadcast
            #pragma unroll
            for (int u = 0; u < 4; u++) vv[u] = Vs[(tx * 4 + u) * 65 + j];  // 2-way
            #pragma unroll
            for (int r = 0; r < 4; r++)
                #pragma unroll
                for (int u = 0; u < 4; u++)
                    O[r][u] = fmaf(pr[r], vv[u], O[r][u]);
        }
    }

    #pragma unroll
    for (int r = 0; r < 4; r++) {
        float inv = 1.f / l[r];
        #pragma unroll
        for (int u = 0; u < 4; u++) O[r][u] *= inv;
    }

    // stage [c][i] in (free) Vs for coalesced float4 store
    __syncthreads();
    #pragma unroll
    for (int u = 0; u < 4; u++)
        #pragma unroll
        for (int r = 0; r < 4; r++)
            Vs[(tx * 4 + u) * 65 + ty * 4 + r] = O[r][u];
    __syncthreads();

    float* ab = g_a + ((size_t)bbi * CC + hh * CHD) * TT;
    for (int e = tid * 4; e < 4096; e += 1024) {
        int c = e >> 6, i = e & 63;
        float* vp = &Vs[c * 65 + i];
        *(float4*)(ab + (size_t)c * TT + t0 + i) =
            make_float4(vp[0], vp[1], vp[2], vp[3]);
    }
}

// ---------------------------------------------------------------------------
extern "C" void kernel_launch(void* const* d_in, const int* in_sizes, int n_in,
                              void* d_out, int out_size) {
    (void)in_sizes; (void)n_in; (void)out_size;
    const float* x      = (const float*)d_in[0];
    const float* gamma  = (const float*)d_in[1];
    const float* beta   = (const float*)d_in[2];
    const float* w_qkv  = (const float*)d_in[3];
    const float* b_qkv  = (const float*)d_in[4];
    const float* w_proj = (const float*)d_in[5];
    const float* b_proj = (const float*)d_in[6];
    float* out = (float*)d_out;

    cudaFuncSetAttribute(attn_kernel,
                         cudaFuncAttributeMaxDynamicSharedMemorySize, ATTN_SMEM);

    void *ph, *pqkv, *pa;
    cudaGetSymbolAddress(&ph, g_h);
    cudaGetSymbolAddress(&pqkv, g_qkv);
    cudaGetSymbolAddress(&pa, g_a);

    gn_kernel<<<BB * NGRP, 256>>>(x, gamma, beta);
    gemm_kernel<false><<<dim3(TT / 64, (3 * CC) / 64, BB), 256>>>(
        w_qkv, (const float*)ph, b_qkv, nullptr, (float*)pqkv, 3 * CC);
    attn_kernel<<<dim3(TT / 64, BB * NHEADS), 256, ATTN_SMEM>>>();
    gemm_kernel<true><<<dim3(TT / 64, CC / 64, BB), 256>>>(
        w_proj, (const float*)pa, b_proj, x, out, CC);
}

// round 6
// speedup vs baseline: 1.3948x; 1.3948x over previous
#include <cuda_runtime.h>
#include <cuda_bf16.h>
#include <cstdint>

// Problem constants: x (8, 512, 32, 32) -> (b=8, c=512, t=1024)
#define BB 8
#define CC 512
#define TT 1024
#define NHEADS 8
#define CHD 64
#define NGRP 32
#define CPG 16

// Scratch (alloc-free rule: __device__ globals)
__device__ float g_h[BB * CC * TT];        // groupnorm output
__device__ float g_qkv[BB * 3 * CC * TT];  // qkv projections
__device__ float g_a[BB * CC * TT];        // attention output

// ---------------------------------------------------------------------------
// Warp-level tensor-core primitives (base-target: no 'a' feature needed)
// ---------------------------------------------------------------------------
__device__ __forceinline__ uint32_t smem_u32(const void* p) {
    uint32_t a;
    asm("{ .reg .u64 t; cvta.to.shared.u64 t, %1; cvt.u32.u64 %0, t; }"
        : "=r"(a) : "l"(p));
    return a;
}

#define LDSM4(r, addr)                                                        \
    asm volatile("ldmatrix.sync.aligned.m8n8.x4.shared.b16 {%0,%1,%2,%3}, [%4];" \
                 : "=r"((r)[0]), "=r"((r)[1]), "=r"((r)[2]), "=r"((r)[3])     \
                 : "r"(addr))
#define LDSM4T(r, addr)                                                       \
    asm volatile("ldmatrix.sync.aligned.m8n8.x4.trans.shared.b16 {%0,%1,%2,%3}, [%4];" \
                 : "=r"((r)[0]), "=r"((r)[1]), "=r"((r)[2]), "=r"((r)[3])     \
                 : "r"(addr))
#define MMA16816(d, a, b)                                                     \
    asm volatile("mma.sync.aligned.m16n8k16.row.col.f32.bf16.bf16.f32 "       \
                 "{%0,%1,%2,%3}, {%4,%5,%6,%7}, {%8,%9}, {%0,%1,%2,%3};"      \
                 : "+f"((d)[0]), "+f"((d)[1]), "+f"((d)[2]), "+f"((d)[3])     \
                 : "r"((a)[0]), "r"((a)[1]), "r"((a)[2]), "r"((a)[3]),        \
                   "r"((b)[0]), "r"((b)[1]))

__device__ __forceinline__ uint32_t pack_hi(float a, float b, float* ra, float* rb) {
    __nv_bfloat16 ha = __float2bfloat16(a), hb = __float2bfloat16(b);
    *ra = a - __bfloat162float(ha);
    *rb = b - __bfloat162float(hb);
    return ((uint32_t)__bfloat16_as_ushort(hb) << 16) | __bfloat16_as_ushort(ha);
}
__device__ __forceinline__ uint32_t pack2(float a, float b) {
    return ((uint32_t)__bfloat16_as_ushort(__float2bfloat16(b)) << 16) |
           __bfloat16_as_ushort(__float2bfloat16(a));
}

// ---------------------------------------------------------------------------
// GroupNorm (unchanged; passed R1)
// ---------------------------------------------------------------------------
__global__ __launch_bounds__(256) void gn_kernel(const float* __restrict__ x,
                                                 const float* __restrict__ gamma,
                                                 const float* __restrict__ beta) {
    int bg = blockIdx.x;
    const float* src = x + (size_t)bg * (CPG * TT);
    float* dst = g_h + (size_t)bg * (CPG * TT);
    int tid = threadIdx.x;
    float s = 0.f, ss = 0.f;
    for (int i = tid * 4; i < CPG * TT; i += 256 * 4) {
        float4 v = *(const float4*)(src + i);
        s += v.x + v.y + v.z + v.w;
        ss += v.x * v.x + v.y * v.y + v.z * v.z + v.w * v.w;
    }
    #pragma unroll
    for (int off = 16; off; off >>= 1) {
        s += __shfl_xor_sync(0xffffffffu, s, off);
        ss += __shfl_xor_sync(0xffffffffu, ss, off);
    }
    __shared__ float ws[8], wss[8];
    __shared__ float sh_mean, sh_r;
    int warp = tid >> 5, lane = tid & 31;
    if (lane == 0) { ws[warp] = s; wss[warp] = ss; }
    __syncthreads();
    if (tid == 0) {
        float S = 0.f, SS = 0.f;
        #pragma unroll
        for (int i = 0; i < 8; i++) { S += ws[i]; SS += wss[i]; }
        const float inv_n = 1.f / (CPG * TT);
        float mean = S * inv_n;
        float var = SS * inv_n - mean * mean;
        sh_mean = mean;
        sh_r = rsqrtf(var + 1e-5f);
    }
    __syncthreads();
    float mean = sh_mean, r = sh_r;
    int g = bg & (NGRP - 1);
    for (int i = tid * 4; i < CPG * TT; i += 256 * 4) {
        int ch = g * CPG + (i >> 10);
        float gm = gamma[ch] * r;
        float bt = beta[ch] - mean * gm;
        float4 v = *(const float4*)(src + i);
        float4 o;
        o.x = v.x * gm + bt; o.y = v.y * gm + bt;
        o.z = v.z * gm + bt; o.w = v.w * gm + bt;
        *(float4*)(dst + i) = o;
    }
}

// ---------------------------------------------------------------------------
// Tensor-core GEMM (mma.sync bf16-split): Out[b][o][t] = W[o][c] X[b][c][t]
// + bias (+resid). CTA tile 128(M o)x128(N t), K chunks of 64 in smem as
// bf16 hi/lo (split in-flight from fp32). 8 warps (4M x 2N), warp tile 32x64.
// 3 MMAs per (A,B) pair: hh + hl + lh into fp32 accumulators.
// ---------------------------------------------------------------------------
#define AS_STRIDE 72    // bf16 units; 144B rows (16B-aligned, swizzle-free)
#define BS_STRIDE 136   // bf16 units; 272B rows
#define A_BYTES (128 * AS_STRIDE * 2)       // 18432
#define B_BYTES (64 * BS_STRIDE * 2)        // 17408
#define O_AH 0
#define O_AL (O_AH + A_BYTES)               // 18432
#define O_BH (O_AL + A_BYTES)               // 36864
#define O_BL (O_BH + B_BYTES)               // 54272
#define GSMEM (O_BL + B_BYTES)              // 71680 (> 128*132*4 epilogue)
#define CS_STRIDE 132

template <bool RES>
__global__ __launch_bounds__(256) void hmma_gemm(const float* __restrict__ W,
                                                 const float* __restrict__ X,
                                                 const float* __restrict__ bias,
                                                 const float* __restrict__ resid,
                                                 float* __restrict__ Out, int Odim) {
    extern __shared__ char smem[];
    const uint32_t sb = smem_u32(smem);
    __nv_bfloat16* Ah = (__nv_bfloat16*)(smem + O_AH);
    __nv_bfloat16* Al = (__nv_bfloat16*)(smem + O_AL);
    __nv_bfloat16* Bh = (__nv_bfloat16*)(smem + O_BH);
    __nv_bfloat16* Bl = (__nv_bfloat16*)(smem + O_BL);

    int nt = blockIdx.x, mt = blockIdx.y, b = blockIdx.z;
    int o0 = mt << 7, t0 = nt << 7;
    const float* Xb = X + (size_t)b * CC * TT;
    int tid = threadIdx.x, wid = tid >> 5, lane = tid & 31;
    int wm = wid >> 1, wn = wid & 1;     // warp grid 4(M) x 2(N)

    float acc[2][8][4] = {};             // [m16 tile][n8 tile][frag]

    for (int kc = 0; kc < CC; kc += 64) {
        // ---- fill: A = W[o0..o0+127][kc..kc+63], split hi/lo ----
        #pragma unroll
        for (int i = tid; i < 2048; i += 256) {
            int row = i >> 4, c4 = (i & 15) << 2;
            float4 v = *(const float4*)(W + (size_t)(o0 + row) * CC + kc + c4);
            float lx, ly, lz, lw;
            uint32_t h01 = pack_hi(v.x, v.y, &lx, &ly);
            uint32_t h23 = pack_hi(v.z, v.w, &lz, &lw);
            int si = row * AS_STRIDE + c4;
            *(uint2*)(Ah + si) = make_uint2(h01, h23);
            *(uint2*)(Al + si) = make_uint2(pack2(lx, ly), pack2(lz, lw));
        }
        // ---- fill: B = X[kc..kc+63][t0..t0+127] ----
        #pragma unroll
        for (int i = tid; i < 2048; i += 256) {
            int row = i >> 5, t4 = (i & 31) << 2;
            float4 v = *(const float4*)(Xb + (size_t)(kc + row) * TT + t0 + t4);
            float lx, ly, lz, lw;
            uint32_t h01 = pack_hi(v.x, v.y, &lx, &ly);
            uint32_t h23 = pack_hi(v.z, v.w, &lz, &lw);
            int si = row * BS_STRIDE + t4;
            *(uint2*)(Bh + si) = make_uint2(h01, h23);
            *(uint2*)(Bl + si) = make_uint2(pack2(lx, ly), pack2(lz, lw));
        }
        __syncthreads();

        // ---- compute: 4 k16-steps ----
        #pragma unroll
        for (int ks = 0; ks < 4; ks++) {
            int k0 = ks << 4;
            // A fragments (2 m16 tiles, hi+lo)
            uint32_t ah[2][4], al[2][4];
            int arow = (wm << 5) + (lane & 15);
            int acol = k0 + ((lane >> 4) << 3);
            #pragma unroll
            for (int m = 0; m < 2; m++) {
                uint32_t ad = sb + O_AH +
                    (uint32_t)(((arow + m * 16) * AS_STRIDE + acol) << 1);
                LDSM4(ah[m], ad);
                LDSM4(al[m], ad + (O_AL - O_AH));
            }
            // B fragments per n16 tile, then 3-term MMAs
            int brow = k0 + (lane & 15);
            int bcol = (wn << 6) + ((lane >> 4) << 3);
            #pragma unroll
            for (int n = 0; n < 4; n++) {
                uint32_t bd = sb + O_BH +
                    (uint32_t)((brow * BS_STRIDE + bcol + n * 16) << 1);
                uint32_t bh[4], bl[4];
                LDSM4T(bh, bd);
                LDSM4T(bl, bd + (O_BL - O_BH));
                #pragma unroll
                for (int h = 0; h < 2; h++) {
                    uint32_t* ph = bh + h * 2;
                    uint32_t* pl = bl + h * 2;
                    #pragma unroll
                    for (int m = 0; m < 2; m++) {
                        float* c = acc[m][n * 2 + h];
                        MMA16816(c, ah[m], ph);
                        MMA16816(c, ah[m], pl);
                        MMA16816(c, al[m], ph);
                    }
                }
            }
        }
        __syncthreads();
    }

    // ---- epilogue: stage C in smem for coalesced stores ----
    float* Cs = (float*)smem;
    #pragma unroll
    for (int m = 0; m < 2; m++)
        #pragma unroll
        for (int n8 = 0; n8 < 8; n8++) {
            int r0 = (wm << 5) + m * 16 + (lane >> 2);
            int c0 = (wn << 6) + n8 * 8 + ((lane & 3) << 1);
            float* c = acc[m][n8];
            Cs[r0 * CS_STRIDE + c0] = c[0];
            Cs[r0 * CS_STRIDE + c0 + 1] = c[1];
            Cs[(r0 + 8) * CS_STRIDE + c0] = c[2];
            Cs[(r0 + 8) * CS_STRIDE + c0 + 1] = c[3];
        }
    __syncthreads();
    #pragma unroll
    for (int i = tid; i < 4096; i += 256) {
        int row = i >> 5, c4 = (i & 31) << 2;
        int o = o0 + row;
        float bs = bias[o];
        float4 v = *(const float4*)&Cs[row * CS_STRIDE + c4];
        v.x += bs; v.y += bs; v.z += bs; v.w += bs;
        size_t off = ((size_t)b * Odim + o) * TT + t0 + c4;
        if (RES) {
            float4 rv = *(const float4*)(resid + off);
            v.x += rv.x; v.y += rv.y; v.z += rv.z; v.w += rv.w;
        }
        *(float4*)(Out + off) = v;
    }
}

// ---------------------------------------------------------------------------
// Flash attention fp32 (unchanged; passed R1)
// ---------------------------------------------------------------------------
#define ATTN_SMEM ((4096 * 3 + 64 * 65) * 4)

__global__ __launch_bounds__(256) void attn_kernel() {
    extern __shared__ float sm[];
    float* Qs = sm;
    float* Ks = Qs + 4096;
    float* Vs = Ks + 4096;
    float* Ps = Vs + 64 * 65;

    int it = blockIdx.x;
    int hd = blockIdx.y;
    int bbi = hd >> 3, hh = hd & 7;
    const float* qb = g_qkv + (size_t)bbi * (3 * CC * TT) + (size_t)(hh * 3 * CHD) * TT;
    const float* kb = qb + CHD * TT;
    const float* vb = kb + CHD * TT;
    int t0 = it << 6;
    int tid = threadIdx.x, tx = tid & 15, ty = tid >> 4;

    for (int e = tid * 4; e < 4096; e += 1024) {
        int c = e >> 6, i = e & 63;
        *(float4*)&Qs[c * 64 + i] = *(const float4*)(qb + (size_t)c * TT + t0 + i);
    }

    float m[4] = {-1e30f, -1e30f, -1e30f, -1e30f};
    float l[4] = {};
    float O[4][4] = {};

    for (int s0 = 0; s0 < TT; s0 += 64) {
        __syncthreads();
        for (int e = tid * 4; e < 4096; e += 1024) {
            int c = e >> 6, j = e & 63;
            *(float4*)&Ks[c * 64 + j] = *(const float4*)(kb + (size_t)c * TT + s0 + j);
            float4 vv = *(const float4*)(vb + (size_t)c * TT + s0 + j);
            float* vp = &Vs[c * 65 + j];
            vp[0] = vv.x; vp[1] = vv.y; vp[2] = vv.z; vp[3] = vv.w;
        }
        __syncthreads();

        float sc[4][4] = {};
        #pragma unroll 8
        for (int c = 0; c < 64; c++) {
            float4 q4 = *(const float4*)&Qs[c * 64 + (ty << 2)];
            float4 k4 = *(const float4*)&Ks[c * 64 + (tx << 2)];
            float qv[4] = {q4.x, q4.y, q4.z, q4.w};
            float kv[4] = {k4.x, k4.y, k4.z, k4.w};
            #pragma unroll
            for (int r = 0; r < 4; r++)
                #pragma unroll
                for (int u = 0; u < 4; u++)
                    sc[r][u] = fmaf(qv[r], kv[u], sc[r][u]);
        }

        #pragma unroll
        for (int r = 0; r < 4; r++) {
            float mx = -1e30f;
            #pragma unroll
            for (int u = 0; u < 4; u++) {
                sc[r][u] *= 0.125f;
                mx = fmaxf(mx, sc[r][u]);
            }
            #pragma unroll
            for (int off = 8; off; off >>= 1)
                mx = fmaxf(mx, __shfl_xor_sync(0xffffffffu, mx, off));
            float mn = fmaxf(m[r], mx);
            float corr = __expf(m[r] - mn);
            m[r] = mn;
            float rs = 0.f;
            #pragma unroll
            for (int u = 0; u < 4; u++) {
                float p = __expf(sc[r][u] - mn);
                sc[r][u] = p;
                rs += p;
            }
            #pragma unroll
            for (int off = 8; off; off >>= 1)
                rs += __shfl_xor_sync(0xffffffffu, rs, off);
            l[r] = l[r] * corr + rs;
            #pragma unroll
            for (int u = 0; u < 4; u++) O[r][u] *= corr;
            *(float4*)&Ps[(ty * 4 + r) * 64 + (tx << 2)] =
                make_float4(sc[r][0], sc[r][1], sc[r][2], sc[r][3]);
        }
        __syncthreads();

        #pragma unroll 4
        for (int j = 0; j < 64; j++) {
            float pr[4], vv[4];
            #pragma unroll
            for (int r = 0; r < 4; r++) pr[r] = Ps[(ty * 4 + r) * 64 + j];
            #pragma unroll
            for (int u = 0; u < 4; u++) vv[u] = Vs[(tx * 4 + u) * 65 + j];
            #pragma unroll
            for (int r = 0; r < 4; r++)
                #pragma unroll
                for (int u = 0; u < 4; u++)
                    O[r][u] = fmaf(pr[r], vv[u], O[r][u]);
        }
    }

    #pragma unroll
    for (int r = 0; r < 4; r++) {
        float inv = 1.f / l[r];
        #pragma unroll
        for (int u = 0; u < 4; u++) O[r][u] *= inv;
    }

    __syncthreads();
    #pragma unroll
    for (int u = 0; u < 4; u++)
        #pragma unroll
        for (int r = 0; r < 4; r++)
            Vs[(tx * 4 + u) * 65 + ty * 4 + r] = O[r][u];
    __syncthreads();

    float* ab = g_a + ((size_t)bbi * CC + hh * CHD) * TT;
    for (int e = tid * 4; e < 4096; e += 1024) {
        int c = e >> 6, i = e & 63;
        float* vp = &Vs[c * 65 + i];
        *(float4*)(ab + (size_t)c * TT + t0 + i) =
            make_float4(vp[0], vp[1], vp[2], vp[3]);
    }
}

// ---------------------------------------------------------------------------
extern "C" void kernel_launch(void* const* d_in, const int* in_sizes, int n_in,
                              void* d_out, int out_size) {
    (void)in_sizes; (void)n_in; (void)out_size;
    const float* x      = (const float*)d_in[0];
    const float* gamma  = (const float*)d_in[1];
    const float* beta   = (const float*)d_in[2];
    const float* w_qkv  = (const float*)d_in[3];
    const float* b_qkv  = (const float*)d_in[4];
    const float* w_proj = (const float*)d_in[5];
    const float* b_proj = (const float*)d_in[6];
    float* out = (float*)d_out;

    cudaFuncSetAttribute(attn_kernel,
                         cudaFuncAttributeMaxDynamicSharedMemorySize, ATTN_SMEM);
    cudaFuncSetAttribute(hmma_gemm<false>,
                         cudaFuncAttributeMaxDynamicSharedMemorySize, GSMEM);
    cudaFuncSetAttribute(hmma_gemm<true>,
                         cudaFuncAttributeMaxDynamicSharedMemorySize, GSMEM);

    void *ph, *pqkv, *pa;
    cudaGetSymbolAddress(&ph, g_h);
    cudaGetSymbolAddress(&pqkv, g_qkv);
    cudaGetSymbolAddress(&pa, g_a);

    gn_kernel<<<BB * NGRP, 256>>>(x, gamma, beta);
    hmma_gemm<false><<<dim3(TT / 128, (3 * CC) / 128, BB), 256, GSMEM>>>(
        w_qkv, (const float*)ph, b_qkv, nullptr, (float*)pqkv, 3 * CC);
    attn_kernel<<<dim3(TT / 64, BB * NHEADS), 256, ATTN_SMEM>>>();
    hmma_gemm<true><<<dim3(TT / 128, CC / 128, BB), 256, GSMEM>>>(
        w_proj, (const float*)pa, b_proj, x, out, CC);
}

// round 7
// speedup vs baseline: 2.3101x; 1.6563x over previous
#include <cuda_runtime.h>
#include <cuda_bf16.h>
#include <cstdint>

// Problem constants: x (8, 512, 32, 32) -> (b=8, c=512, t=1024)
#define BB 8
#define CC 512
#define TT 1024
#define NHEADS 8
#define CHD 64
#define NGRP 32
#define CPG 16

// Scratch (alloc-free rule: __device__ globals)
__device__ float g_h[BB * CC * TT];        // groupnorm output
__device__ float g_qkv[BB * 3 * CC * TT];  // qkv projections
__device__ float g_a[BB * CC * TT];        // attention output

// ---------------------------------------------------------------------------
// Warp-level tensor-core primitives (base-target; verified in R6)
// ---------------------------------------------------------------------------
__device__ __forceinline__ uint32_t smem_u32(const void* p) {
    uint32_t a;
    asm("{ .reg .u64 t; cvta.to.shared.u64 t, %1; cvt.u32.u64 %0, t; }"
        : "=r"(a) : "l"(p));
    return a;
}

#define LDSM4(r, addr)                                                        \
    asm volatile("ldmatrix.sync.aligned.m8n8.x4.shared.b16 {%0,%1,%2,%3}, [%4];" \
                 : "=r"((r)[0]), "=r"((r)[1]), "=r"((r)[2]), "=r"((r)[3])     \
                 : "r"(addr))
#define LDSM4T(r, addr)                                                       \
    asm volatile("ldmatrix.sync.aligned.m8n8.x4.trans.shared.b16 {%0,%1,%2,%3}, [%4];" \
                 : "=r"((r)[0]), "=r"((r)[1]), "=r"((r)[2]), "=r"((r)[3])     \
                 : "r"(addr))
#define MMA16816(d, a, b)                                                     \
    asm volatile("mma.sync.aligned.m16n8k16.row.col.f32.bf16.bf16.f32 "       \
                 "{%0,%1,%2,%3}, {%4,%5,%6,%7}, {%8,%9}, {%0,%1,%2,%3};"      \
                 : "+f"((d)[0]), "+f"((d)[1]), "+f"((d)[2]), "+f"((d)[3])     \
                 : "r"((a)[0]), "r"((a)[1]), "r"((a)[2]), "r"((a)[3]),        \
                   "r"((b)[0]), "r"((b)[1]))

__device__ __forceinline__ uint32_t pack_hi(float a, float b, float* ra, float* rb) {
    __nv_bfloat16 ha = __float2bfloat16(a), hb = __float2bfloat16(b);
    *ra = a - __bfloat162float(ha);
    *rb = b - __bfloat162float(hb);
    return ((uint32_t)__bfloat16_as_ushort(hb) << 16) | __bfloat16_as_ushort(ha);
}
__device__ __forceinline__ uint32_t pack2(float a, float b) {
    return ((uint32_t)__bfloat16_as_ushort(__float2bfloat16(b)) << 16) |
           __bfloat16_as_ushort(__float2bfloat16(a));
}

// ---------------------------------------------------------------------------
// GroupNorm (unchanged; passing since R1)
// ---------------------------------------------------------------------------
__global__ __launch_bounds__(256) void gn_kernel(const float* __restrict__ x,
                                                 const float* __restrict__ gamma,
                                                 const float* __restrict__ beta) {
    int bg = blockIdx.x;
    const float* src = x + (size_t)bg * (CPG * TT);
    float* dst = g_h + (size_t)bg * (CPG * TT);
    int tid = threadIdx.x;
    float s = 0.f, ss = 0.f;
    for (int i = tid * 4; i < CPG * TT; i += 256 * 4) {
        float4 v = *(const float4*)(src + i);
        s += v.x + v.y + v.z + v.w;
        ss += v.x * v.x + v.y * v.y + v.z * v.z + v.w * v.w;
    }
    #pragma unroll
    for (int off = 16; off; off >>= 1) {
        s += __shfl_xor_sync(0xffffffffu, s, off);
        ss += __shfl_xor_sync(0xffffffffu, ss, off);
    }
    __shared__ float ws[8], wss[8];
    __shared__ float sh_mean, sh_r;
    int warp = tid >> 5, lane = tid & 31;
    if (lane == 0) { ws[warp] = s; wss[warp] = ss; }
    __syncthreads();
    if (tid == 0) {
        float S = 0.f, SS = 0.f;
        #pragma unroll
        for (int i = 0; i < 8; i++) { S += ws[i]; SS += wss[i]; }
        const float inv_n = 1.f / (CPG * TT);
        float mean = S * inv_n;
        float var = SS * inv_n - mean * mean;
        sh_mean = mean;
        sh_r = rsqrtf(var + 1e-5f);
    }
    __syncthreads();
    float mean = sh_mean, r = sh_r;
    int g = bg & (NGRP - 1);
    for (int i = tid * 4; i < CPG * TT; i += 256 * 4) {
        int ch = g * CPG + (i >> 10);
        float gm = gamma[ch] * r;
        float bt = beta[ch] - mean * gm;
        float4 v = *(const float4*)(src + i);
        float4 o;
        o.x = v.x * gm + bt; o.y = v.y * gm + bt;
        o.z = v.z * gm + bt; o.w = v.w * gm + bt;
        *(float4*)(dst + i) = o;
    }
}

// ---------------------------------------------------------------------------
// Tensor-core GEMM (unchanged; R6: passed, 47.9us proj / tensor 43%)
// ---------------------------------------------------------------------------
#define AS_STRIDE 72
#define BS_STRIDE 136
#define A_BYTES (128 * AS_STRIDE * 2)
#define B_BYTES (64 * BS_STRIDE * 2)
#define O_AH 0
#define O_AL (O_AH + A_BYTES)
#define O_BH (O_AL + A_BYTES)
#define O_BL (O_BH + B_BYTES)
#define GSMEM (O_BL + B_BYTES)
#define CS_STRIDE 132

template <bool RES>
__global__ __launch_bounds__(256) void hmma_gemm(const float* __restrict__ W,
                                                 const float* __restrict__ X,
                                                 const float* __restrict__ bias,
                                                 const float* __restrict__ resid,
                                                 float* __restrict__ Out, int Odim) {
    extern __shared__ char smem[];
    const uint32_t sb = smem_u32(smem);
    __nv_bfloat16* Ah = (__nv_bfloat16*)(smem + O_AH);
    __nv_bfloat16* Al = (__nv_bfloat16*)(smem + O_AL);
    __nv_bfloat16* Bh = (__nv_bfloat16*)(smem + O_BH);
    __nv_bfloat16* Bl = (__nv_bfloat16*)(smem + O_BL);

    int nt = blockIdx.x, mt = blockIdx.y, b = blockIdx.z;
    int o0 = mt << 7, t0 = nt << 7;
    const float* Xb = X + (size_t)b * CC * TT;
    int tid = threadIdx.x, wid = tid >> 5, lane = tid & 31;
    int wm = wid >> 1, wn = wid & 1;

    float acc[2][8][4] = {};

    for (int kc = 0; kc < CC; kc += 64) {
        #pragma unroll
        for (int i = tid; i < 2048; i += 256) {
            int row = i >> 4, c4 = (i & 15) << 2;
            float4 v = *(const float4*)(W + (size_t)(o0 + row) * CC + kc + c4);
            float lx, ly, lz, lw;
            uint32_t h01 = pack_hi(v.x, v.y, &lx, &ly);
            uint32_t h23 = pack_hi(v.z, v.w, &lz, &lw);
            int si = row * AS_STRIDE + c4;
            *(uint2*)(Ah + si) = make_uint2(h01, h23);
            *(uint2*)(Al + si) = make_uint2(pack2(lx, ly), pack2(lz, lw));
        }
        #pragma unroll
        for (int i = tid; i < 2048; i += 256) {
            int row = i >> 5, t4 = (i & 31) << 2;
            float4 v = *(const float4*)(Xb + (size_t)(kc + row) * TT + t0 + t4);
            float lx, ly, lz, lw;
            uint32_t h01 = pack_hi(v.x, v.y, &lx, &ly);
            uint32_t h23 = pack_hi(v.z, v.w, &lz, &lw);
            int si = row * BS_STRIDE + t4;
            *(uint2*)(Bh + si) = make_uint2(h01, h23);
            *(uint2*)(Bl + si) = make_uint2(pack2(lx, ly), pack2(lz, lw));
        }
        __syncthreads();

        #pragma unroll
        for (int ks = 0; ks < 4; ks++) {
            int k0 = ks << 4;
            uint32_t ah[2][4], al[2][4];
            int arow = (wm << 5) + (lane & 15);
            int acol = k0 + ((lane >> 4) << 3);
            #pragma unroll
            for (int m = 0; m < 2; m++) {
                uint32_t ad = sb + O_AH +
                    (uint32_t)(((arow + m * 16) * AS_STRIDE + acol) << 1);
                LDSM4(ah[m], ad);
                LDSM4(al[m], ad + (O_AL - O_AH));
            }
            int brow = k0 + (lane & 15);
            int bcol = (wn << 6) + ((lane >> 4) << 3);
            #pragma unroll
            for (int n = 0; n < 4; n++) {
                uint32_t bd = sb + O_BH +
                    (uint32_t)((brow * BS_STRIDE + bcol + n * 16) << 1);
                uint32_t bh[4], bl[4];
                LDSM4T(bh, bd);
                LDSM4T(bl, bd + (O_BL - O_BH));
                #pragma unroll
                for (int h = 0; h < 2; h++) {
                    uint32_t* ph = bh + h * 2;
                    uint32_t* pl = bl + h * 2;
                    #pragma unroll
                    for (int m = 0; m < 2; m++) {
                        float* c = acc[m][n * 2 + h];
                        MMA16816(c, ah[m], ph);
                        MMA16816(c, ah[m], pl);
                        MMA16816(c, al[m], ph);
                    }
                }
            }
        }
        __syncthreads();
    }

    float* Cs = (float*)smem;
    #pragma unroll
    for (int m = 0; m < 2; m++)
        #pragma unroll
        for (int n8 = 0; n8 < 8; n8++) {
            int r0 = (wm << 5) + m * 16 + (lane >> 2);
            int c0 = (wn << 6) + n8 * 8 + ((lane & 3) << 1);
            float* c = acc[m][n8];
            Cs[r0 * CS_STRIDE + c0] = c[0];
            Cs[r0 * CS_STRIDE + c0 + 1] = c[1];
            Cs[(r0 + 8) * CS_STRIDE + c0] = c[2];
            Cs[(r0 + 8) * CS_STRIDE + c0 + 1] = c[3];
        }
    __syncthreads();
    #pragma unroll
    for (int i = tid; i < 4096; i += 256) {
        int row = i >> 5, c4 = (i & 31) << 2;
        int o = o0 + row;
        float bs = bias[o];
        float4 v = *(const float4*)&Cs[row * CS_STRIDE + c4];
        v.x += bs; v.y += bs; v.z += bs; v.w += bs;
        size_t off = ((size_t)b * Odim + o) * TT + t0 + c4;
        if (RES) {
            float4 rv = *(const float4*)(resid + off);
            v.x += rv.x; v.y += rv.y; v.z += rv.z; v.w += rv.w;
        }
        *(float4*)(Out + off) = v;
    }
}

// ---------------------------------------------------------------------------
// Flash attention on HMMA (bf16-split, FA2 register pipeline).
// Block = (128-query tile, head). 8 warps; warp w owns q-rows [w*16, w*16+16).
// smem: Qh/Ql [128 i][72 d], Kh/Kl [64 c][72 j], Vh/Vl [64 j][72 c],
//       fp32 staging [64][66] for the Q/V transposes.
// ---------------------------------------------------------------------------
#define A2_QS 72
#define A2_QH 0
#define A2_QL 18432
#define A2_KH 36864
#define A2_KL 46080
#define A2_VH 55296
#define A2_VL 64512
#define A2_ST 73728
#define A2_SMEM (A2_ST + 64 * 66 * 4)   // 90624
#define A2_CS 68

__global__ __launch_bounds__(256) void attn_hmma() {
    extern __shared__ char smem[];
    const uint32_t sb = smem_u32(smem);
    __nv_bfloat16* Qh = (__nv_bfloat16*)(smem + A2_QH);
    __nv_bfloat16* Ql = (__nv_bfloat16*)(smem + A2_QL);
    __nv_bfloat16* Kh = (__nv_bfloat16*)(smem + A2_KH);
    __nv_bfloat16* Kl = (__nv_bfloat16*)(smem + A2_KL);
    __nv_bfloat16* Vh = (__nv_bfloat16*)(smem + A2_VH);
    __nv_bfloat16* Vl = (__nv_bfloat16*)(smem + A2_VL);
    float* stg = (float*)(smem + A2_ST);    // [64][66]

    int it = blockIdx.x;          // q tile (128)
    int hd = blockIdx.y;          // 0..63
    int bbi = hd >> 3, hh = hd & 7;
    const float* qb = g_qkv + (size_t)bbi * (3 * CC * TT) + (size_t)(hh * 3 * CHD) * TT;
    const float* kb = qb + CHD * TT;
    const float* vb = kb + CHD * TT;
    int t0 = it << 7;
    int tid = threadIdx.x, wid = tid >> 5, lane = tid & 31;

    // ---- Q: transpose [c][t] -> [i][d], scale by 2^-3 (exact), split ----
    #pragma unroll
    for (int ch = 0; ch < 2; ch++) {
        int i0 = ch << 6;
        #pragma unroll
        for (int e = tid; e < 4096; e += 256) {
            int c = e >> 6, i = e & 63;
            stg[i * 66 + c] = qb[(size_t)c * TT + t0 + i0 + i] * 0.125f;
        }
        __syncthreads();
        #pragma unroll
        for (int e = tid; e < 1024; e += 256) {
            int row = e >> 4, c4 = (e & 15) << 2;
            const float* p = &stg[row * 66 + c4];
            float lx, ly, lz, lw;
            uint32_t h01 = pack_hi(p[0], p[1], &lx, &ly);
            uint32_t h23 = pack_hi(p[2], p[3], &lz, &lw);
            int si = (i0 + row) * A2_QS + c4;
            *(uint2*)(Qh + si) = make_uint2(h01, h23);
            *(uint2*)(Ql + si) = make_uint2(pack2(lx, ly), pack2(lz, lw));
        }
        __syncthreads();
    }

    float m0 = -1e30f, m1 = -1e30f, l0 = 0.f, l1 = 0.f;
    float o[8][4] = {};
    int arow = (wid << 4) + (lane & 15);
    int csel = (lane >> 4) << 3;

    for (int s0 = 0; s0 < TT; s0 += 64) {
        __syncthreads();    // prior iteration's ldmatrix reads complete
        // K fill (direct [c][j], split in-flight)
        #pragma unroll
        for (int e = tid; e < 2048; e += 256) {
            int c = e >> 5, j2 = (e & 31) << 1;
            const float* p = kb + (size_t)c * TT + s0 + j2;
            float la, lbv;
            uint32_t h = pack_hi(p[0], p[1], &la, &lbv);
            int si = c * A2_QS + j2;
            *(uint32_t*)(Kh + si) = h;
            *(uint32_t*)(Kl + si) = pack2(la, lbv);
        }
        // V stage transpose [c][j] -> [j][c]
        #pragma unroll
        for (int e = tid; e < 4096; e += 256) {
            int c = e >> 6, j = e & 63;
            stg[j * 66 + c] = vb[(size_t)c * TT + s0 + j];
        }
        __syncthreads();
        #pragma unroll
        for (int e = tid; e < 1024; e += 256) {
            int row = e >> 4, c4 = (e & 15) << 2;
            const float* p = &stg[row * 66 + c4];
            float lx, ly, lz, lw;
            uint32_t h01 = pack_hi(p[0], p[1], &lx, &ly);
            uint32_t h23 = pack_hi(p[2], p[3], &lz, &lw);
            int si = row * A2_QS + c4;
            *(uint2*)(Vh + si) = make_uint2(h01, h23);
            *(uint2*)(Vl + si) = make_uint2(pack2(lx, ly), pack2(lz, lw));
        }
        __syncthreads();

        // ---- S = Q K (d contraction, 4 k16 steps), 3-term split ----
        float s[8][4] = {};
        #pragma unroll
        for (int k16 = 0; k16 < 4; k16++) {
            uint32_t qh4[4], ql4[4];
            uint32_t qa = sb + A2_QH + (uint32_t)((arow * A2_QS + (k16 << 4) + csel) << 1);
            LDSM4(qh4, qa);
            LDSM4(ql4, qa + (A2_QL - A2_QH));
            int brow = (k16 << 4) + (lane & 15);
            #pragma unroll
            for (int n16 = 0; n16 < 4; n16++) {
                uint32_t ba = sb + A2_KH +
                    (uint32_t)((brow * A2_QS + (n16 << 4) + csel) << 1);
                uint32_t bh4[4], bl4[4];
                LDSM4T(bh4, ba);
                LDSM4T(bl4, ba + (A2_KL - A2_KH));
                #pragma unroll
                for (int h = 0; h < 2; h++) {
                    float* c = s[n16 * 2 + h];
                    MMA16816(c, qh4, bh4 + h * 2);
                    MMA16816(c, qh4, bl4 + h * 2);
                    MMA16816(c, ql4, bh4 + h * 2);
                }
            }
        }

        // ---- online softmax (rows r=lane>>2 and r+8, within 4-lane groups) ----
        float mx0 = -1e30f, mx1 = -1e30f;
        #pragma unroll
        for (int t = 0; t < 8; t++) {
            mx0 = fmaxf(mx0, fmaxf(s[t][0], s[t][1]));
            mx1 = fmaxf(mx1, fmaxf(s[t][2], s[t][3]));
        }
        #pragma unroll
        for (int off = 1; off <= 2; off <<= 1) {
            mx0 = fmaxf(mx0, __shfl_xor_sync(0xffffffffu, mx0, off));
            mx1 = fmaxf(mx1, __shfl_xor_sync(0xffffffffu, mx1, off));
        }
        float nm0 = fmaxf(m0, mx0), nm1 = fmaxf(m1, mx1);
        float cr0 = __expf(m0 - nm0), cr1 = __expf(m1 - nm1);
        m0 = nm0; m1 = nm1;
        float rs0 = 0.f, rs1 = 0.f;
        #pragma unroll
        for (int t = 0; t < 8; t++) {
            s[t][0] = __expf(s[t][0] - m0); rs0 += s[t][0];
            s[t][1] = __expf(s[t][1] - m0); rs0 += s[t][1];
            s[t][2] = __expf(s[t][2] - m1); rs1 += s[t][2];
            s[t][3] = __expf(s[t][3] - m1); rs1 += s[t][3];
        }
        #pragma unroll
        for (int off = 1; off <= 2; off <<= 1) {
            rs0 += __shfl_xor_sync(0xffffffffu, rs0, off);
            rs1 += __shfl_xor_sync(0xffffffffu, rs1, off);
        }
        l0 = l0 * cr0 + rs0;
        l1 = l1 * cr1 + rs1;
        #pragma unroll
        for (int t = 0; t < 8; t++) {
            o[t][0] *= cr0; o[t][1] *= cr0;
            o[t][2] *= cr1; o[t][3] *= cr1;
        }

        // ---- O += P V (j contraction, 4 k16 steps), P from S-frags ----
        #pragma unroll
        for (int t = 0; t < 4; t++) {
            uint32_t ah4[4], al4[4];
            float e0, e1;
            ah4[0] = pack_hi(s[2 * t][0], s[2 * t][1], &e0, &e1);
            al4[0] = pack2(e0, e1);
            ah4[1] = pack_hi(s[2 * t][2], s[2 * t][3], &e0, &e1);
            al4[1] = pack2(e0, e1);
            ah4[2] = pack_hi(s[2 * t + 1][0], s[2 * t + 1][1], &e0, &e1);
            al4[2] = pack2(e0, e1);
            ah4[3] = pack_hi(s[2 * t + 1][2], s[2 * t + 1][3], &e0, &e1);
            al4[3] = pack2(e0, e1);
            int vrow = (t << 4) + (lane & 15);
            #pragma unroll
            for (int n16 = 0; n16 < 4; n16++) {
                uint32_t va = sb + A2_VH +
                    (uint32_t)((vrow * A2_QS + (n16 << 4) + csel) << 1);
                uint32_t vh4[4], vl4[4];
                LDSM4T(vh4, va);
                LDSM4T(vl4, va + (A2_VL - A2_VH));
                #pragma unroll
                for (int h = 0; h < 2; h++) {
                    float* c = o[n16 * 2 + h];
                    MMA16816(c, ah4, vh4 + h * 2);
                    MMA16816(c, ah4, vl4 + h * 2);
                    MMA16816(c, al4, vh4 + h * 2);
                }
            }
        }
    }

    // ---- normalize + epilogue via smem (reuses Q region) ----
    float inv0 = 1.f / l0, inv1 = 1.f / l1;
    __syncthreads();
    float* Cs = (float*)smem;
    int r0 = (wid << 4) + (lane >> 2);
    int cb = (lane & 3) << 1;
    #pragma unroll
    for (int t = 0; t < 8; t++) {
        int c0 = t * 8 + cb;
        Cs[r0 * A2_CS + c0] = o[t][0] * inv0;
        Cs[r0 * A2_CS + c0 + 1] = o[t][1] * inv0;
        Cs[(r0 + 8) * A2_CS + c0] = o[t][2] * inv1;
        Cs[(r0 + 8) * A2_CS + c0 + 1] = o[t][3] * inv1;
    }
    __syncthreads();
    float* ab = g_a + ((size_t)bbi * CC + hh * CHD) * TT;
    #pragma unroll
    for (int e = tid; e < 2048; e += 256) {
        int c = e >> 5, i4 = (e & 31) << 2;
        float4 v;
        v.x = Cs[(i4 + 0) * A2_CS + c];
        v.y = Cs[(i4 + 1) * A2_CS + c];
        v.z = Cs[(i4 + 2) * A2_CS + c];
        v.w = Cs[(i4 + 3) * A2_CS + c];
        *(float4*)(ab + (size_t)c * TT + t0 + i4) = v;
    }
}

// ---------------------------------------------------------------------------
extern "C" void kernel_launch(void* const* d_in, const int* in_sizes, int n_in,
                              void* d_out, int out_size) {
    (void)in_sizes; (void)n_in; (void)out_size;
    const float* x      = (const float*)d_in[0];
    const float* gamma  = (const float*)d_in[1];
    const float* beta   = (const float*)d_in[2];
    const float* w_qkv  = (const float*)d_in[3];
    const float* b_qkv  = (const float*)d_in[4];
    const float* w_proj = (const float*)d_in[5];
    const float* b_proj = (const float*)d_in[6];
    float* out = (float*)d_out;

    cudaFuncSetAttribute(attn_hmma,
                         cudaFuncAttributeMaxDynamicSharedMemorySize, A2_SMEM);
    cudaFuncSetAttribute(hmma_gemm<false>,
                         cudaFuncAttributeMaxDynamicSharedMemorySize, GSMEM);
    cudaFuncSetAttribute(hmma_gemm<true>,
                         cudaFuncAttributeMaxDynamicSharedMemorySize, GSMEM);

    void *ph, *pqkv, *pa;
    cudaGetSymbolAddress(&ph, g_h);
    cudaGetSymbolAddress(&pqkv, g_qkv);
    cudaGetSymbolAddress(&pa, g_a);

    gn_kernel<<<BB * NGRP, 256>>>(x, gamma, beta);
    hmma_gemm<false><<<dim3(TT / 128, (3 * CC) / 128, BB), 256, GSMEM>>>(
        w_qkv, (const float*)ph, b_qkv, nullptr, (float*)pqkv, 3 * CC);
    attn_hmma<<<dim3(TT / 128, BB * NHEADS), 256, A2_SMEM>>>();
    hmma_gemm<true><<<dim3(TT / 128, CC / 128, BB), 256, GSMEM>>>(
        w_proj, (const float*)pa, b_proj, x, out, CC);
}